// round 12
// baseline (speedup 1.0000x reference)
#include <cuda_runtime.h>
#include <cuda_bf16.h>
#include <cuda_fp16.h>
#include <cstdint>

#define NN   20000
#define EE   320000
#define MM   3
#define IN_  128
#define HH   4
#define DD   64
#define HD_  256
#define HID_ 128

// ================= scratch (static device globals; no allocation) =================
// INVARIANT: g_cnt is all-zero at every kernel_launch entry (zero-initialized at load;
// k_scan re-zeroes each counter after consuming it each replay).
__device__ __align__(16) __half g_feat16[(size_t)MM * NN * HD_];
__device__ __align__(16) float g_z[(size_t)MM * NN * HD_];
__device__ __align__(16) __nv_bfloat16 g_zhi[(size_t)MM * NN * HD_];
__device__ __align__(16) __nv_bfloat16 g_hhi[(size_t)NN * IN_];
__device__ __align__(16) __nv_bfloat16 g_hlo[(size_t)NN * IN_];
__device__ __align__(16) __nv_bfloat16 g_Whi[(size_t)MM * HD_ * IN_];   // [m][n][k]  (W^T, k-contig)
__device__ __align__(16) __nv_bfloat16 g_Wlo[(size_t)MM * HD_ * IN_];
__device__ __align__(16) __nv_bfloat16 g_W1hi[(size_t)HID_ * HD_];      // [n][k]
__device__ __align__(16) float g_el[MM * NN * HH];
__device__ __align__(16) float g_er[MM * NN * HH];
__device__ int   g_cnt[MM * NN];
__device__ int   g_off[MM * (NN + 1)];
__device__ int   g_cur[MM * NN];
__device__ int   g_esrc[MM * EE];
__device__ float g_wsum[MM];

// ================= HMMA helper (plain sm_80+ mma.sync — no 'a' features) =================
#define MMA_BF16(c, a0, a1, a2, a3, b0, b1) \
    asm volatile("mma.sync.aligned.m16n8k16.row.col.f32.bf16.bf16.f32 " \
                 "{%0,%1,%2,%3}, {%4,%5,%6,%7}, {%8,%9}, {%0,%1,%2,%3};" \
                 : "+f"((c)[0]), "+f"((c)[1]), "+f"((c)[2]), "+f"((c)[3]) \
                 : "r"(a0), "r"(a1), "r"(a2), "r"(a3), "r"(b0), "r"(b1))

template <int PITCHW, int NK>
__device__ __forceinline__ void gemm_pass(const uint32_t* __restrict__ A,
                                          const uint32_t* __restrict__ B,
                                          float acc[2][8][4], int warpM0, int warpN0,
                                          int g, int tg) {
#pragma unroll
    for (int kk = 0; kk < NK; kk++) {
        const int kw = kk * 8 + tg;
        uint32_t a[2][4];
#pragma unroll
        for (int mf = 0; mf < 2; mf++) {
            const int rb = (warpM0 + mf * 16 + g) * PITCHW + kw;
            a[mf][0] = A[rb];
            a[mf][1] = A[rb + 8 * PITCHW];
            a[mf][2] = A[rb + 4];
            a[mf][3] = A[rb + 8 * PITCHW + 4];
        }
#pragma unroll
        for (int nf = 0; nf < 8; nf++) {
            const int nb = (warpN0 + nf * 8 + g) * PITCHW + kw;
            const uint32_t b0 = B[nb];
            const uint32_t b1 = B[nb + 4];
            MMA_BF16(acc[0][nf], a[0][0], a[0][1], a[0][2], a[0][3], b0, b1);
            MMA_BF16(acc[1][nf], a[1][0], a[1][1], a[1][2], a[1][3], b0, b1);
        }
    }
}

// ================= K0: fused prep =================
// blocks [0,96): tiled transpose-convert of W -> g_Whi/g_Wlo (coalesced both sides)
// blocks [96, ...): h conv, W1 conv, dst histogram (g_cnt pre-zeroed invariant), wsum=0
#define WTILES (MM * (IN_ / 32) * (HD_ / 32))   // 96
__global__ void k_prep(const float* __restrict__ h, const float* __restrict__ W,
                       const float* __restrict__ W1, const int* __restrict__ dst) {
    const int b = blockIdx.x, t = threadIdx.x;
    if (b < WTILES) {
        __shared__ float tile[32][33];
        const int m = b / 32;
        const int kt = (b % 32) / 8, nt = (b % 32) % 8;
        const int c = t & 31, r0 = t >> 5;   // c: 0..31, r0: 0..7
        const float* Wm = W + (size_t)m * IN_ * HD_;
#pragma unroll
        for (int q = 0; q < 4; q++) {
            int r = r0 + q * 8;
            tile[r][c] = Wm[(kt * 32 + r) * HD_ + nt * 32 + c];   // coalesced read
        }
        __syncthreads();
        __nv_bfloat16* Oh = g_Whi + (size_t)m * HD_ * IN_;
        __nv_bfloat16* Ol = g_Wlo + (size_t)m * HD_ * IN_;
#pragma unroll
        for (int q = 0; q < 4; q++) {
            int nl = r0 + q * 8;            // local n
            int kl = c;                     // local k (consecutive per lane -> coalesced)
            float x = tile[kl][nl];
            __nv_bfloat16 hi = __float2bfloat16(x);
            size_t o = (size_t)(nt * 32 + nl) * IN_ + kt * 32 + kl;
            Oh[o] = hi;
            Ol[o] = __float2bfloat16(x - __bfloat162float(hi));
        }
        return;
    }
    int i = (b - WTILES) * blockDim.x + t;
    if (i < NN * IN_) {
        float x = h[i];
        __nv_bfloat16 hi = __float2bfloat16(x);
        g_hhi[i] = hi;
        g_hlo[i] = __float2bfloat16(x - __bfloat162float(hi));
    }
    if (i < HD_ * HID_) {
        int k = i / HID_, n = i - (i / HID_) * HID_;
        g_W1hi[(size_t)n * HD_ + k] = __float2bfloat16(W1[i]);
    }
    if (i < MM * EE) {
        int m = i / EE;
        atomicAdd(&g_cnt[m * NN + dst[i]], 1);
    }
    if (i < MM) g_wsum[i] = 0.0f;
}

// ================= K1: feat = h @ W (HMMA hi/lo x3) + FUSED el/er  grid (157, 2, 3) ====
#define F_PITCH 68
#define F_ALO   8704
#define F_BHI   17408
#define F_BLO   26112
#define F_SMEM_BYTES (4 * 128 * F_PITCH * 4)   // 139264

__global__ void __launch_bounds__(256, 1) k_mma_feat(const float* __restrict__ attn_l,
                                                     const float* __restrict__ attn_r) {
    extern __shared__ uint32_t smw[];
    __shared__ float sAL[128], sAR[128];
    const int m = blockIdx.z;
    const int row0 = blockIdx.x * 128;
    const int ncol0 = blockIdx.y * 128;
    const int tid = threadIdx.x;
    const int lane = tid & 31, warp = tid >> 5;
    const int g = lane >> 2, tg = lane & 3;
    const int warpM0 = (warp & 3) * 32;
    const int warpN0 = (warp >> 2) * 64;

    if (tid < 128) {
        sAL[tid] = attn_l[m * HD_ + ncol0 + tid];
        sAR[tid] = attn_r[m * HD_ + ncol0 + tid];
    }

    {
        const int r = tid >> 1, half = tid & 1;
        uint4* dAH = (uint4*)smw;
        uint4* dAL = (uint4*)(smw + F_ALO);
        uint4* dBH = (uint4*)(smw + F_BHI);
        uint4* dBL = (uint4*)(smw + F_BLO);
        const int db = r * 17 + half * 8;
        const int gr = row0 + r;
        if (gr < NN) {
            const uint4* sh = (const uint4*)g_hhi + (size_t)gr * 16 + half * 8;
            const uint4* sl = (const uint4*)g_hlo + (size_t)gr * 16 + half * 8;
#pragma unroll
            for (int j = 0; j < 8; j++) { dAH[db + j] = sh[j]; dAL[db + j] = sl[j]; }
        } else {
            uint4 zz = make_uint4(0u, 0u, 0u, 0u);
#pragma unroll
            for (int j = 0; j < 8; j++) { dAH[db + j] = zz; dAL[db + j] = zz; }
        }
        const uint4* wh = (const uint4*)g_Whi + ((size_t)m * HD_ + ncol0 + r) * 16 + half * 8;
        const uint4* wl = (const uint4*)g_Wlo + ((size_t)m * HD_ + ncol0 + r) * 16 + half * 8;
#pragma unroll
        for (int j = 0; j < 8; j++) { dBH[db + j] = wh[j]; dBL[db + j] = wl[j]; }
    }
    __syncthreads();

    float acc[2][8][4];
#pragma unroll
    for (int i = 0; i < 2; i++)
#pragma unroll
        for (int j = 0; j < 8; j++)
#pragma unroll
            for (int q = 0; q < 4; q++) acc[i][j][q] = 0.0f;

    gemm_pass<F_PITCH, 8>(smw, smw + F_BHI, acc, warpM0, warpN0, g, tg);          // AH*BH
    gemm_pass<F_PITCH, 8>(smw, smw + F_BLO, acc, warpM0, warpN0, g, tg);          // AH*BL
    gemm_pass<F_PITCH, 8>(smw + F_ALO, smw + F_BHI, acc, warpM0, warpN0, g, tg);  // AL*BH

    float pl[4] = {0.f, 0.f, 0.f, 0.f};
    float pr[4] = {0.f, 0.f, 0.f, 0.f};
#pragma unroll
    for (int mf = 0; mf < 2; mf++) {
        const int grow = row0 + warpM0 + mf * 16 + g;
#pragma unroll
        for (int nf = 0; nf < 8; nf++) {
            const int lc = warpN0 + nf * 8 + tg * 2;
            const int gcol = ncol0 + lc;
            if (grow < NN) {
                __half2 hh;
                hh.x = __float2half_rn(acc[mf][nf][0]);
                hh.y = __float2half_rn(acc[mf][nf][1]);
                *(__half2*)&g_feat16[((size_t)m * NN + grow) * HD_ + gcol] = hh;
            }
            if (grow + 8 < NN) {
                __half2 hh;
                hh.x = __float2half_rn(acc[mf][nf][2]);
                hh.y = __float2half_rn(acc[mf][nf][3]);
                *(__half2*)&g_feat16[((size_t)m * NN + grow + 8) * HD_ + gcol] = hh;
            }
            pl[mf * 2]     += acc[mf][nf][0] * sAL[lc] + acc[mf][nf][1] * sAL[lc + 1];
            pl[mf * 2 + 1] += acc[mf][nf][2] * sAL[lc] + acc[mf][nf][3] * sAL[lc + 1];
            pr[mf * 2]     += acc[mf][nf][0] * sAR[lc] + acc[mf][nf][1] * sAR[lc + 1];
            pr[mf * 2 + 1] += acc[mf][nf][2] * sAR[lc] + acc[mf][nf][3] * sAR[lc + 1];
        }
    }
#pragma unroll
    for (int s = 0; s < 4; s++) {
        pl[s] += __shfl_xor_sync(0xffffffffu, pl[s], 1);
        pl[s] += __shfl_xor_sync(0xffffffffu, pl[s], 2);
        pr[s] += __shfl_xor_sync(0xffffffffu, pr[s], 1);
        pr[s] += __shfl_xor_sync(0xffffffffu, pr[s], 2);
    }
    if (tg == 0) {
        const int head = 2 * blockIdx.y + (warp >> 2);
#pragma unroll
        for (int s = 0; s < 4; s++) {
            const int grow = row0 + warpM0 + g + s * 8;
            if (grow < NN) {
                g_el[(size_t)(m * NN + grow) * HH + head] = pl[s];
                g_er[(size_t)(m * NN + grow) * HH + head] = pr[s];
            }
        }
    }
}

// ================= K2: single-kernel scan (3 blocks x 1024 thr, 20 counts/thread) ======
// Also re-zeroes g_cnt (restores the entry invariant for the next replay).
__global__ void __launch_bounds__(1024) k_scan() {
    const int m = blockIdx.x, t = threadIdx.x;
    __shared__ int wsc[32];
    const int CH = 20;   // 1024*20 = 20480 >= NN
    const int base = t * CH;
    int c[CH];
    int s = 0;
#pragma unroll
    for (int i = 0; i < CH; i++) {
        int idx = base + i;
        c[i] = (idx < NN) ? g_cnt[m * NN + idx] : 0;
        s += c[i];
    }
    const int lane = t & 31, wid = t >> 5;
    int v = s;
#pragma unroll
    for (int o = 1; o < 32; o <<= 1) {
        int u = __shfl_up_sync(0xffffffffu, v, o);
        if (lane >= o) v += u;
    }
    if (lane == 31) wsc[wid] = v;
    __syncthreads();
    if (wid == 0) {
        int w = wsc[lane];
#pragma unroll
        for (int o = 1; o < 32; o <<= 1) {
            int u = __shfl_up_sync(0xffffffffu, w, o);
            if (lane >= o) w += u;
        }
        wsc[lane] = w;
    }
    __syncthreads();
    int ex = v - s + (wid ? wsc[wid - 1] : 0);
#pragma unroll
    for (int i = 0; i < CH; i++) {
        int idx = base + i;
        if (idx < NN) {
            g_off[m * (NN + 1) + idx] = ex;
            g_cur[m * NN + idx] = ex;
            ex += c[i];
            g_cnt[m * NN + idx] = 0;   // restore invariant
        }
    }
    if (t == 1023) g_off[m * (NN + 1) + NN] = wsc[31];
}

__global__ void k_scatter(const int* __restrict__ src, const int* __restrict__ dst) {
    int i = blockIdx.x * blockDim.x + threadIdx.x;
    if (i >= MM * EE) return;
    int m = i / EE;
    int p = atomicAdd(&g_cur[m * NN + dst[i]], 1);
    g_esrc[(size_t)m * EE + p] = src[i];
}

// ================= K4: single-pass edge softmax + aggregation (normalize at end) =======
__global__ void k_agg(const float* __restrict__ bias) {
    __shared__ float sW[8][32][4];
    __shared__ int   sS[8][32];
    const int wip = threadIdx.x >> 5;
    const int lane = threadIdx.x & 31;
    int gw = (blockIdx.x * blockDim.x + threadIdx.x) >> 5;
    if (gw >= MM * NN) return;
    int m = gw / NN, n = gw - m * NN;
    int start = g_off[m * (NN + 1) + n];
    int end   = g_off[m * (NN + 1) + n + 1];
    const size_t mbase = (size_t)m * NN;
    float4 er4 = *(const float4*)&g_er[(mbase + n) * HH];
    const int* esrc = &g_esrc[(size_t)m * EE];
    const int head = lane >> 3;
    const uint4* fv = (const uint4*)g_feat16;

    float acc[8];
#pragma unroll
    for (int k = 0; k < 8; k++) acc[k] = 0.f;
    float dsum = 0.f;

    for (int j = start; j < end; j += 32) {
        int myE = j + lane;
        int cnt = min(32, end - j);
        int smy = 0;
        float w0 = 0.f, w1 = 0.f, w2 = 0.f, w3 = 0.f;
        if (myE < end) {
            smy = esrc[myE];
            float4 el4 = *(const float4*)&g_el[(mbase + smy) * HH];
            float e0 = el4.x + er4.x; e0 = e0 > 0.f ? e0 : 0.2f * e0; w0 = __expf(e0);
            float e1 = el4.y + er4.y; e1 = e1 > 0.f ? e1 : 0.2f * e1; w1 = __expf(e1);
            float e2 = el4.z + er4.z; e2 = e2 > 0.f ? e2 : 0.2f * e2; w2 = __expf(e2);
            float e3 = el4.w + er4.w; e3 = e3 > 0.f ? e3 : 0.2f * e3; w3 = __expf(e3);
        }
        sS[wip][lane] = smy;
        *(float4*)&sW[wip][lane][0] = make_float4(w0, w1, w2, w3);
        __syncwarp();
        const int cnt4 = (cnt + 3) & ~3;
        for (int t = 0; t < cnt4; t += 4) {
            int s0 = sS[wip][t + 0];
            int s1 = sS[wip][t + 1];
            int s2 = sS[wip][t + 2];
            int s3 = sS[wip][t + 3];
            float wa = sW[wip][t + 0][head];
            float wb = sW[wip][t + 1][head];
            float wc = sW[wip][t + 2][head];
            float wd = sW[wip][t + 3][head];
            uint4 p0 = fv[(mbase + s0) * (HD_ / 8) + lane];
            uint4 p1 = fv[(mbase + s1) * (HD_ / 8) + lane];
            uint4 p2 = fv[(mbase + s2) * (HD_ / 8) + lane];
            uint4 p3 = fv[(mbase + s3) * (HD_ / 8) + lane];
            dsum += (wa + wb) + (wc + wd);
            {
                const __half2* hp = (const __half2*)&p0;
                float2 q0 = __half22float2(hp[0]), q1 = __half22float2(hp[1]);
                float2 q2 = __half22float2(hp[2]), q3 = __half22float2(hp[3]);
                acc[0] = fmaf(wa, q0.x, acc[0]); acc[1] = fmaf(wa, q0.y, acc[1]);
                acc[2] = fmaf(wa, q1.x, acc[2]); acc[3] = fmaf(wa, q1.y, acc[3]);
                acc[4] = fmaf(wa, q2.x, acc[4]); acc[5] = fmaf(wa, q2.y, acc[5]);
                acc[6] = fmaf(wa, q3.x, acc[6]); acc[7] = fmaf(wa, q3.y, acc[7]);
            }
            {
                const __half2* hp = (const __half2*)&p1;
                float2 q0 = __half22float2(hp[0]), q1 = __half22float2(hp[1]);
                float2 q2 = __half22float2(hp[2]), q3 = __half22float2(hp[3]);
                acc[0] = fmaf(wb, q0.x, acc[0]); acc[1] = fmaf(wb, q0.y, acc[1]);
                acc[2] = fmaf(wb, q1.x, acc[2]); acc[3] = fmaf(wb, q1.y, acc[3]);
                acc[4] = fmaf(wb, q2.x, acc[4]); acc[5] = fmaf(wb, q2.y, acc[5]);
                acc[6] = fmaf(wb, q3.x, acc[6]); acc[7] = fmaf(wb, q3.y, acc[7]);
            }
            {
                const __half2* hp = (const __half2*)&p2;
                float2 q0 = __half22float2(hp[0]), q1 = __half22float2(hp[1]);
                float2 q2 = __half22float2(hp[2]), q3 = __half22float2(hp[3]);
                acc[0] = fmaf(wc, q0.x, acc[0]); acc[1] = fmaf(wc, q0.y, acc[1]);
                acc[2] = fmaf(wc, q1.x, acc[2]); acc[3] = fmaf(wc, q1.y, acc[3]);
                acc[4] = fmaf(wc, q2.x, acc[4]); acc[5] = fmaf(wc, q2.y, acc[5]);
                acc[6] = fmaf(wc, q3.x, acc[6]); acc[7] = fmaf(wc, q3.y, acc[7]);
            }
            {
                const __half2* hp = (const __half2*)&p3;
                float2 q0 = __half22float2(hp[0]), q1 = __half22float2(hp[1]);
                float2 q2 = __half22float2(hp[2]), q3 = __half22float2(hp[3]);
                acc[0] = fmaf(wd, q0.x, acc[0]); acc[1] = fmaf(wd, q0.y, acc[1]);
                acc[2] = fmaf(wd, q1.x, acc[2]); acc[3] = fmaf(wd, q1.y, acc[3]);
                acc[4] = fmaf(wd, q2.x, acc[4]); acc[5] = fmaf(wd, q2.y, acc[5]);
                acc[6] = fmaf(wd, q3.x, acc[6]); acc[7] = fmaf(wd, q3.y, acc[7]);
            }
        }
        __syncwarp();
    }

    const float rd = 1.f / fmaxf(dsum, 1e-9f);
    const int c0 = lane * 8;
    const float* bv = &bias[m * HD_ + c0];
    float o[8];
#pragma unroll
    for (int k = 0; k < 8; k++) o[k] = fmaf(acc[k], rd, bv[k]);
    size_t zb = (mbase + n) * HD_ + c0;
    *(float4*)&g_z[zb]     = make_float4(o[0], o[1], o[2], o[3]);
    *(float4*)&g_z[zb + 4] = make_float4(o[4], o[5], o[6], o[7]);
    __nv_bfloat162 zh[4];
#pragma unroll
    for (int k = 0; k < 4; k++) {
        zh[k].x = __float2bfloat16(o[2 * k]);
        zh[k].y = __float2bfloat16(o[2 * k + 1]);
    }
    *(uint4*)&g_zhi[zb] = *(uint4*)zh;
}

// ================= K5: semantic GEMM (HMMA, single bf16 pass) + fused epilogue =========
#define S_PITCH 132
#define S_S1    16896
#define S_SMEM_BYTES (2 * 128 * S_PITCH * 4)   // 135168

__global__ void __launch_bounds__(256, 1) k_mma_sem(const float* __restrict__ b1,
                                                    const float* __restrict__ W2) {
    extern __shared__ uint32_t smw[];
    __shared__ float sB1[HID_], sW2[HID_], sred[8];
    const int m = blockIdx.z;
    const int row0 = blockIdx.x * 128;
    const int tid = threadIdx.x;
    const int lane = tid & 31, warp = tid >> 5;
    const int g = lane >> 2, tg = lane & 3;
    const int warpM0 = (warp & 3) * 32;
    const int warpN0 = (warp >> 2) * 64;

    if (tid < HID_) { sB1[tid] = b1[tid]; sW2[tid] = W2[tid]; }

    const int r = tid >> 1, half = tid & 1;
    const int db = r * 33 + half * 16;
    const int gr = row0 + r;
    {
        uint4* dA = (uint4*)smw;
        uint4* dB1 = (uint4*)(smw + S_S1);
        if (gr < NN) {
            const uint4* sh = (const uint4*)g_zhi + ((size_t)m * NN + gr) * 32 + half * 16;
#pragma unroll
            for (int j = 0; j < 16; j++) dA[db + j] = sh[j];
        } else {
            uint4 zz = make_uint4(0u, 0u, 0u, 0u);
#pragma unroll
            for (int j = 0; j < 16; j++) dA[db + j] = zz;
        }
        const uint4* w1h = (const uint4*)g_W1hi + (size_t)r * 32 + half * 16;
#pragma unroll
        for (int j = 0; j < 16; j++) dB1[db + j] = w1h[j];
    }
    __syncthreads();

    float acc[2][8][4];
#pragma unroll
    for (int i = 0; i < 2; i++)
#pragma unroll
        for (int j = 0; j < 8; j++)
#pragma unroll
            for (int q = 0; q < 4; q++) acc[i][j][q] = 0.0f;

    gemm_pass<S_PITCH, 16>(smw, smw + S_S1, acc, warpM0, warpN0, g, tg);   // A * W1

    float p = 0.f;
#pragma unroll
    for (int mf = 0; mf < 2; mf++) {
        const int grow = row0 + warpM0 + mf * 16 + g;
        const bool v0 = grow < NN, v1 = grow + 8 < NN;
#pragma unroll
        for (int nf = 0; nf < 8; nf++) {
            const int col = warpN0 + nf * 8 + tg * 2;
            if (v0) {
                p = fmaf(tanhf(acc[mf][nf][0] + sB1[col]),     sW2[col],     p);
                p = fmaf(tanhf(acc[mf][nf][1] + sB1[col + 1]), sW2[col + 1], p);
            }
            if (v1) {
                p = fmaf(tanhf(acc[mf][nf][2] + sB1[col]),     sW2[col],     p);
                p = fmaf(tanhf(acc[mf][nf][3] + sB1[col + 1]), sW2[col + 1], p);
            }
        }
    }
#pragma unroll
    for (int o = 16; o; o >>= 1) p += __shfl_xor_sync(0xffffffffu, p, o);
    if (lane == 0) sred[warp] = p;
    __syncthreads();
    if (tid == 0) {
        float t = 0.f;
#pragma unroll
        for (int w = 0; w < 8; w++) t += sred[w];
        atomicAdd(&g_wsum[m], t);
    }
}

// ================= K6: combine (beta computed per block) =================
__global__ void k_comb(float* __restrict__ out) {
    __shared__ float sb[3];
    if (threadIdx.x == 0) {
        float w0 = g_wsum[0] / (float)NN;
        float w1 = g_wsum[1] / (float)NN;
        float w2 = g_wsum[2] / (float)NN;
        float mx = fmaxf(w0, fmaxf(w1, w2));
        float e0 = __expf(w0 - mx), e1 = __expf(w1 - mx), e2 = __expf(w2 - mx);
        float s = e0 + e1 + e2;
        sb[0] = e0 / s; sb[1] = e1 / s; sb[2] = e2 / s;
    }
    __syncthreads();
    int i = blockIdx.x * blockDim.x + threadIdx.x;
    const int TOT = NN * HD_ / 4;
    if (i >= TOT) return;
    float b0 = sb[0], b1 = sb[1], b2 = sb[2];
    const float4* z = (const float4*)g_z;
    const size_t S = (size_t)NN * (HD_ / 4);
    float4 a = z[i], b = z[S + i], c = z[2 * S + i];
    ((float4*)out)[i] = make_float4(b0 * a.x + b1 * b.x + b2 * c.x,
                                    b0 * a.y + b1 * b.y + b2 * c.y,
                                    b0 * a.z + b1 * b.z + b2 * c.z,
                                    b0 * a.w + b1 * b.w + b2 * c.w);
}

// ================= launcher =================
extern "C" void kernel_launch(void* const* d_in, const int* in_sizes, int n_in,
                              void* d_out, int out_size) {
    const float* h    = (const float*)d_in[0];
    const int*   src  = (const int*)d_in[1];
    const int*   dst  = (const int*)d_in[2];
    const float* W    = (const float*)d_in[3];
    const float* al   = (const float*)d_in[4];
    const float* ar   = (const float*)d_in[5];
    const float* bias = (const float*)d_in[6];
    const float* sW1  = (const float*)d_in[7];
    const float* sb1  = (const float*)d_in[8];
    const float* sW2  = (const float*)d_in[9];
    float* out = (float*)d_out;

    cudaFuncSetAttribute(k_mma_feat, cudaFuncAttributeMaxDynamicSharedMemorySize, F_SMEM_BYTES);
    cudaFuncSetAttribute(k_mma_sem, cudaFuncAttributeMaxDynamicSharedMemorySize, S_SMEM_BYTES);

    const int NTILES = (NN + 127) / 128;   // 157

    k_prep<<<WTILES + (NN * IN_ + 255) / 256, 256>>>(h, W, sW1, dst);

    dim3 gf(NTILES, 2, MM);
    k_mma_feat<<<gf, 256, F_SMEM_BYTES>>>(al, ar);

    k_scan<<<MM, 1024>>>();
    k_scatter<<<(MM * EE + 255) / 256, 256>>>(src, dst);
    k_agg<<<(MM * NN * 32 + 255) / 256, 256>>>(bias);

    dim3 gs(NTILES, 1, MM);
    k_mma_sem<<<gs, 256, S_SMEM_BYTES>>>(sb1, sW2);
    k_comb<<<(NN * HD_ / 4 + 255) / 256, 256>>>(out);
}

// round 14
// speedup vs baseline: 1.0947x; 1.0947x over previous
#include <cuda_runtime.h>
#include <cuda_bf16.h>
#include <cuda_fp16.h>
#include <cstdint>

#define NN   20000
#define EE   320000
#define MM   3
#define IN_  128
#define HH   4
#define DD   64
#define HD_  256
#define HID_ 128

#define SCB  2048
#define NSB  ((NN + SCB - 1) / SCB)   // 10

// ================= scratch (static device globals; no allocation) =================
__device__ __align__(16) __half g_feat16[(size_t)MM * NN * HD_];
__device__ __align__(16) float g_z[(size_t)MM * NN * HD_];
__device__ __align__(16) __nv_bfloat16 g_zhi[(size_t)MM * NN * HD_];
__device__ __align__(16) __nv_bfloat16 g_hhi[(size_t)NN * IN_];
__device__ __align__(16) __nv_bfloat16 g_hlo[(size_t)NN * IN_];
__device__ __align__(16) __nv_bfloat16 g_Whi[(size_t)MM * HD_ * IN_];   // [m][n][k]  (W^T, k-contig)
__device__ __align__(16) __nv_bfloat16 g_Wlo[(size_t)MM * HD_ * IN_];
__device__ __align__(16) __nv_bfloat16 g_W1hi[(size_t)HID_ * HD_];      // [n][k]
__device__ __align__(16) float g_el[MM * NN * HH];
__device__ __align__(16) float g_er[MM * NN * HH];
__device__ int   g_cnt[MM * NN];
__device__ int   g_off[MM * (NN + 1)];
__device__ int   g_cur[MM * NN];
__device__ int   g_esrc[MM * EE];
__device__ int   g_bsum[MM * NSB];
__device__ float g_wsum[MM];

// ================= HMMA helper (plain sm_80+ mma.sync — no 'a' features) =================
#define MMA_BF16(c, a0, a1, a2, a3, b0, b1) \
    asm volatile("mma.sync.aligned.m16n8k16.row.col.f32.bf16.bf16.f32 " \
                 "{%0,%1,%2,%3}, {%4,%5,%6,%7}, {%8,%9}, {%0,%1,%2,%3};" \
                 : "+f"((c)[0]), "+f"((c)[1]), "+f"((c)[2]), "+f"((c)[3]) \
                 : "r"(a0), "r"(a1), "r"(a2), "r"(a3), "r"(b0), "r"(b1))

template <int PITCHW, int NK>
__device__ __forceinline__ void gemm_pass(const uint32_t* __restrict__ A,
                                          const uint32_t* __restrict__ B,
                                          float acc[2][8][4], int warpM0, int warpN0,
                                          int g, int tg) {
#pragma unroll
    for (int kk = 0; kk < NK; kk++) {
        const int kw = kk * 8 + tg;
        uint32_t a[2][4];
#pragma unroll
        for (int mf = 0; mf < 2; mf++) {
            const int rb = (warpM0 + mf * 16 + g) * PITCHW + kw;
            a[mf][0] = A[rb];
            a[mf][1] = A[rb + 8 * PITCHW];
            a[mf][2] = A[rb + 4];
            a[mf][3] = A[rb + 8 * PITCHW + 4];
        }
#pragma unroll
        for (int nf = 0; nf < 8; nf++) {
            const int nb = (warpN0 + nf * 8 + g) * PITCHW + kw;
            const uint32_t b0 = B[nb];
            const uint32_t b1 = B[nb + 4];
            MMA_BF16(acc[0][nf], a[0][0], a[0][1], a[0][2], a[0][3], b0, b1);
            MMA_BF16(acc[1][nf], a[1][0], a[1][1], a[1][2], a[1][3], b0, b1);
        }
    }
}

// ================= K0: prep — coalesced W transpose tiles + flat conversions ==========
// blocks [0,96): 32x32 tiled transpose-convert of W -> g_Whi/g_Wlo (coalesced both sides)
// blocks [96,...): h conv, W1 conv, zero cnt, zero wsum  (hist stays a separate kernel)
#define WTILES (MM * (IN_ / 32) * (HD_ / 32))   // 96
__global__ void k_prep(const float* __restrict__ h, const float* __restrict__ W,
                       const float* __restrict__ W1) {
    const int b = blockIdx.x, t = threadIdx.x;
    if (b < WTILES) {
        __shared__ float tile[32][33];
        const int m = b / 32;
        const int kt = (b % 32) / 8, nt = (b % 32) % 8;
        const int c = t & 31, r0 = t >> 5;   // c: 0..31, r0: 0..7
        const float* Wm = W + (size_t)m * IN_ * HD_;
#pragma unroll
        for (int q = 0; q < 4; q++) {
            int r = r0 + q * 8;
            tile[r][c] = Wm[(kt * 32 + r) * HD_ + nt * 32 + c];   // coalesced read
        }
        __syncthreads();
        __nv_bfloat16* Oh = g_Whi + (size_t)m * HD_ * IN_;
        __nv_bfloat16* Ol = g_Wlo + (size_t)m * HD_ * IN_;
#pragma unroll
        for (int q = 0; q < 4; q++) {
            int nl = r0 + q * 8;            // local n
            int kl = c;                     // local k (consecutive per lane -> coalesced)
            float x = tile[kl][nl];
            __nv_bfloat16 hi = __float2bfloat16(x);
            size_t o = (size_t)(nt * 32 + nl) * IN_ + kt * 32 + kl;
            Oh[o] = hi;
            Ol[o] = __float2bfloat16(x - __bfloat162float(hi));
        }
        return;
    }
    int i = (b - WTILES) * blockDim.x + t;
    if (i < NN * IN_) {
        float x = h[i];
        __nv_bfloat16 hi = __float2bfloat16(x);
        g_hhi[i] = hi;
        g_hlo[i] = __float2bfloat16(x - __bfloat162float(hi));
    }
    if (i < HD_ * HID_) {
        int k = i / HID_, n = i - (i / HID_) * HID_;
        g_W1hi[(size_t)n * HD_ + k] = __float2bfloat16(W1[i]);
    }
    if (i < MM * NN) g_cnt[i] = 0;
    if (i < MM) g_wsum[i] = 0.0f;
}

// ================= K1: histogram — 4 edges/thread (MLP over ATOMG latency) ============
__global__ void k_hist(const int* __restrict__ dst) {
    int base = (blockIdx.x * blockDim.x + threadIdx.x) * 4;
    if (base >= MM * EE) return;
    int d[4];
    int n = min(4, MM * EE - base);
#pragma unroll
    for (int k = 0; k < 4; k++) d[k] = (k < n) ? dst[base + k] : 0;
#pragma unroll
    for (int k = 0; k < 4; k++) {
        if (k < n) {
            int m = (base + k) / EE;
            atomicAdd(&g_cnt[m * NN + d[k]], 1);
        }
    }
}

// ================= K2: feat = h @ W (HMMA hi/lo x3) + FUSED el/er  grid (157, 2, 3) ====
#define F_PITCH 68
#define F_ALO   8704
#define F_BHI   17408
#define F_BLO   26112
#define F_SMEM_BYTES (4 * 128 * F_PITCH * 4)   // 139264

__global__ void __launch_bounds__(256, 1) k_mma_feat(const float* __restrict__ attn_l,
                                                     const float* __restrict__ attn_r) {
    extern __shared__ uint32_t smw[];
    __shared__ float sAL[128], sAR[128];
    const int m = blockIdx.z;
    const int row0 = blockIdx.x * 128;
    const int ncol0 = blockIdx.y * 128;
    const int tid = threadIdx.x;
    const int lane = tid & 31, warp = tid >> 5;
    const int g = lane >> 2, tg = lane & 3;
    const int warpM0 = (warp & 3) * 32;
    const int warpN0 = (warp >> 2) * 64;

    if (tid < 128) {
        sAL[tid] = attn_l[m * HD_ + ncol0 + tid];
        sAR[tid] = attn_r[m * HD_ + ncol0 + tid];
    }

    {
        const int r = tid >> 1, half = tid & 1;
        uint4* dAH = (uint4*)smw;
        uint4* dAL = (uint4*)(smw + F_ALO);
        uint4* dBH = (uint4*)(smw + F_BHI);
        uint4* dBL = (uint4*)(smw + F_BLO);
        const int db = r * 17 + half * 8;
        const int gr = row0 + r;
        if (gr < NN) {
            const uint4* sh = (const uint4*)g_hhi + (size_t)gr * 16 + half * 8;
            const uint4* sl = (const uint4*)g_hlo + (size_t)gr * 16 + half * 8;
#pragma unroll
            for (int j = 0; j < 8; j++) { dAH[db + j] = sh[j]; dAL[db + j] = sl[j]; }
        } else {
            uint4 zz = make_uint4(0u, 0u, 0u, 0u);
#pragma unroll
            for (int j = 0; j < 8; j++) { dAH[db + j] = zz; dAL[db + j] = zz; }
        }
        const uint4* wh = (const uint4*)g_Whi + ((size_t)m * HD_ + ncol0 + r) * 16 + half * 8;
        const uint4* wl = (const uint4*)g_Wlo + ((size_t)m * HD_ + ncol0 + r) * 16 + half * 8;
#pragma unroll
        for (int j = 0; j < 8; j++) { dBH[db + j] = wh[j]; dBL[db + j] = wl[j]; }
    }
    __syncthreads();

    float acc[2][8][4];
#pragma unroll
    for (int i = 0; i < 2; i++)
#pragma unroll
        for (int j = 0; j < 8; j++)
#pragma unroll
            for (int q = 0; q < 4; q++) acc[i][j][q] = 0.0f;

    gemm_pass<F_PITCH, 8>(smw, smw + F_BHI, acc, warpM0, warpN0, g, tg);          // AH*BH
    gemm_pass<F_PITCH, 8>(smw, smw + F_BLO, acc, warpM0, warpN0, g, tg);          // AH*BL
    gemm_pass<F_PITCH, 8>(smw + F_ALO, smw + F_BHI, acc, warpM0, warpN0, g, tg);  // AL*BH

    float pl[4] = {0.f, 0.f, 0.f, 0.f};
    float pr[4] = {0.f, 0.f, 0.f, 0.f};
#pragma unroll
    for (int mf = 0; mf < 2; mf++) {
        const int grow = row0 + warpM0 + mf * 16 + g;
#pragma unroll
        for (int nf = 0; nf < 8; nf++) {
            const int lc = warpN0 + nf * 8 + tg * 2;
            const int gcol = ncol0 + lc;
            if (grow < NN) {
                __half2 hh;
                hh.x = __float2half_rn(acc[mf][nf][0]);
                hh.y = __float2half_rn(acc[mf][nf][1]);
                *(__half2*)&g_feat16[((size_t)m * NN + grow) * HD_ + gcol] = hh;
            }
            if (grow + 8 < NN) {
                __half2 hh;
                hh.x = __float2half_rn(acc[mf][nf][2]);
                hh.y = __float2half_rn(acc[mf][nf][3]);
                *(__half2*)&g_feat16[((size_t)m * NN + grow + 8) * HD_ + gcol] = hh;
            }
            pl[mf * 2]     += acc[mf][nf][0] * sAL[lc] + acc[mf][nf][1] * sAL[lc + 1];
            pl[mf * 2 + 1] += acc[mf][nf][2] * sAL[lc] + acc[mf][nf][3] * sAL[lc + 1];
            pr[mf * 2]     += acc[mf][nf][0] * sAR[lc] + acc[mf][nf][1] * sAR[lc + 1];
            pr[mf * 2 + 1] += acc[mf][nf][2] * sAR[lc] + acc[mf][nf][3] * sAR[lc + 1];
        }
    }
#pragma unroll
    for (int s = 0; s < 4; s++) {
        pl[s] += __shfl_xor_sync(0xffffffffu, pl[s], 1);
        pl[s] += __shfl_xor_sync(0xffffffffu, pl[s], 2);
        pr[s] += __shfl_xor_sync(0xffffffffu, pr[s], 1);
        pr[s] += __shfl_xor_sync(0xffffffffu, pr[s], 2);
    }
    if (tg == 0) {
        const int head = 2 * blockIdx.y + (warp >> 2);
#pragma unroll
        for (int s = 0; s < 4; s++) {
            const int grow = row0 + warpM0 + g + s * 8;
            if (grow < NN) {
                g_el[(size_t)(m * NN + grow) * HH + head] = pl[s];
                g_er[(size_t)(m * NN + grow) * HH + head] = pr[s];
            }
        }
    }
}

// ================= K3-K4: two-phase scan (as in the 235.7 build) =================
__global__ void k_scan1() {
    const int m = blockIdx.y, b = blockIdx.x, t = threadIdx.x;
    __shared__ int sc[256];
    const int base = b * SCB + t * 8;
    int c[8];
    int s = 0;
#pragma unroll
    for (int i = 0; i < 8; i++) {
        int idx = base + i;
        c[i] = (idx < NN) ? g_cnt[m * NN + idx] : 0;
        s += c[i];
    }
    sc[t] = s;
    __syncthreads();
    for (int off = 1; off < 256; off <<= 1) {
        int v = (t >= off) ? sc[t - off] : 0;
        __syncthreads();
        sc[t] += v;
        __syncthreads();
    }
    int ex = t ? sc[t - 1] : 0;
#pragma unroll
    for (int i = 0; i < 8; i++) {
        int idx = base + i;
        if (idx < NN) { g_off[m * (NN + 1) + idx] = ex; ex += c[i]; }
    }
    if (t == 255) g_bsum[m * NSB + b] = sc[255];
}

__global__ void k_scan3() {
    const int m = blockIdx.y, b = blockIdx.x, t = threadIdx.x;
    __shared__ int sbase;
    if (t == 0) {
        int acc = 0;
        for (int i = 0; i < b; i++) acc += g_bsum[m * NSB + i];
        sbase = acc;
        if (b == NSB - 1) {
            int tot = acc;
            for (int i = b; i < NSB; i++) tot += g_bsum[m * NSB + i];
            g_off[m * (NN + 1) + NN] = tot;
        }
    }
    __syncthreads();
    const int base = b * SCB + t * 8;
    const int sb = sbase;
#pragma unroll
    for (int i = 0; i < 8; i++) {
        int idx = base + i;
        if (idx < NN) {
            int v = g_off[m * (NN + 1) + idx] + sb;
            g_off[m * (NN + 1) + idx] = v;
            g_cur[m * NN + idx] = v;
        }
    }
}

// ================= K5: scatter — 4 edges/thread (MLP over ATOMG latency) ==============
__global__ void k_scatter(const int* __restrict__ src, const int* __restrict__ dst) {
    int base = (blockIdx.x * blockDim.x + threadIdx.x) * 4;
    if (base >= MM * EE) return;
    int n = min(4, MM * EE - base);
    int d[4], sc[4];
#pragma unroll
    for (int k = 0; k < 4; k++) {
        d[k]  = (k < n) ? dst[base + k] : 0;
        sc[k] = (k < n) ? src[base + k] : 0;
    }
#pragma unroll
    for (int k = 0; k < 4; k++) {
        if (k < n) {
            int m = (base + k) / EE;
            int p = atomicAdd(&g_cur[m * NN + d[k]], 1);
            g_esrc[(size_t)m * EE + p] = sc[k];
        }
    }
}

// ================= K6: single-pass edge softmax + aggregation (normalize at end) =======
__global__ void k_agg(const float* __restrict__ bias) {
    __shared__ float sW[8][32][4];
    __shared__ int   sS[8][32];
    const int wip = threadIdx.x >> 5;
    const int lane = threadIdx.x & 31;
    int gw = (blockIdx.x * blockDim.x + threadIdx.x) >> 5;
    if (gw >= MM * NN) return;
    int m = gw / NN, n = gw - m * NN;
    int start = g_off[m * (NN + 1) + n];
    int end   = g_off[m * (NN + 1) + n + 1];
    const size_t mbase = (size_t)m * NN;
    float4 er4 = *(const float4*)&g_er[(mbase + n) * HH];
    const int* esrc = &g_esrc[(size_t)m * EE];
    const int head = lane >> 3;
    const uint4* fv = (const uint4*)g_feat16;

    float acc[8];
#pragma unroll
    for (int k = 0; k < 8; k++) acc[k] = 0.f;
    float dsum = 0.f;

    for (int j = start; j < end; j += 32) {
        int myE = j + lane;
        int cnt = min(32, end - j);
        int smy = 0;
        float w0 = 0.f, w1 = 0.f, w2 = 0.f, w3 = 0.f;
        if (myE < end) {
            smy = esrc[myE];
            float4 el4 = *(const float4*)&g_el[(mbase + smy) * HH];
            float e0 = el4.x + er4.x; e0 = e0 > 0.f ? e0 : 0.2f * e0; w0 = __expf(e0);
            float e1 = el4.y + er4.y; e1 = e1 > 0.f ? e1 : 0.2f * e1; w1 = __expf(e1);
            float e2 = el4.z + er4.z; e2 = e2 > 0.f ? e2 : 0.2f * e2; w2 = __expf(e2);
            float e3 = el4.w + er4.w; e3 = e3 > 0.f ? e3 : 0.2f * e3; w3 = __expf(e3);
        }
        sS[wip][lane] = smy;
        *(float4*)&sW[wip][lane][0] = make_float4(w0, w1, w2, w3);
        __syncwarp();
        const int cnt4 = (cnt + 3) & ~3;
        for (int t = 0; t < cnt4; t += 4) {
            int s0 = sS[wip][t + 0];
            int s1 = sS[wip][t + 1];
            int s2 = sS[wip][t + 2];
            int s3 = sS[wip][t + 3];
            float wa = sW[wip][t + 0][head];
            float wb = sW[wip][t + 1][head];
            float wc = sW[wip][t + 2][head];
            float wd = sW[wip][t + 3][head];
            uint4 p0 = fv[(mbase + s0) * (HD_ / 8) + lane];
            uint4 p1 = fv[(mbase + s1) * (HD_ / 8) + lane];
            uint4 p2 = fv[(mbase + s2) * (HD_ / 8) + lane];
            uint4 p3 = fv[(mbase + s3) * (HD_ / 8) + lane];
            dsum += (wa + wb) + (wc + wd);
            {
                const __half2* hp = (const __half2*)&p0;
                float2 q0 = __half22float2(hp[0]), q1 = __half22float2(hp[1]);
                float2 q2 = __half22float2(hp[2]), q3 = __half22float2(hp[3]);
                acc[0] = fmaf(wa, q0.x, acc[0]); acc[1] = fmaf(wa, q0.y, acc[1]);
                acc[2] = fmaf(wa, q1.x, acc[2]); acc[3] = fmaf(wa, q1.y, acc[3]);
                acc[4] = fmaf(wa, q2.x, acc[4]); acc[5] = fmaf(wa, q2.y, acc[5]);
                acc[6] = fmaf(wa, q3.x, acc[6]); acc[7] = fmaf(wa, q3.y, acc[7]);
            }
            {
                const __half2* hp = (const __half2*)&p1;
                float2 q0 = __half22float2(hp[0]), q1 = __half22float2(hp[1]);
                float2 q2 = __half22float2(hp[2]), q3 = __half22float2(hp[3]);
                acc[0] = fmaf(wb, q0.x, acc[0]); acc[1] = fmaf(wb, q0.y, acc[1]);
                acc[2] = fmaf(wb, q1.x, acc[2]); acc[3] = fmaf(wb, q1.y, acc[3]);
                acc[4] = fmaf(wb, q2.x, acc[4]); acc[5] = fmaf(wb, q2.y, acc[5]);
                acc[6] = fmaf(wb, q3.x, acc[6]); acc[7] = fmaf(wb, q3.y, acc[7]);
            }
            {
                const __half2* hp = (const __half2*)&p2;
                float2 q0 = __half22float2(hp[0]), q1 = __half22float2(hp[1]);
                float2 q2 = __half22float2(hp[2]), q3 = __half22float2(hp[3]);
                acc[0] = fmaf(wc, q0.x, acc[0]); acc[1] = fmaf(wc, q0.y, acc[1]);
                acc[2] = fmaf(wc, q1.x, acc[2]); acc[3] = fmaf(wc, q1.y, acc[3]);
                acc[4] = fmaf(wc, q2.x, acc[4]); acc[5] = fmaf(wc, q2.y, acc[5]);
                acc[6] = fmaf(wc, q3.x, acc[6]); acc[7] = fmaf(wc, q3.y, acc[7]);
            }
            {
                const __half2* hp = (const __half2*)&p3;
                float2 q0 = __half22float2(hp[0]), q1 = __half22float2(hp[1]);
                float2 q2 = __half22float2(hp[2]), q3 = __half22float2(hp[3]);
                acc[0] = fmaf(wd, q0.x, acc[0]); acc[1] = fmaf(wd, q0.y, acc[1]);
                acc[2] = fmaf(wd, q1.x, acc[2]); acc[3] = fmaf(wd, q1.y, acc[3]);
                acc[4] = fmaf(wd, q2.x, acc[4]); acc[5] = fmaf(wd, q2.y, acc[5]);
                acc[6] = fmaf(wd, q3.x, acc[6]); acc[7] = fmaf(wd, q3.y, acc[7]);
            }
        }
        __syncwarp();
    }

    const float rd = 1.f / fmaxf(dsum, 1e-9f);
    const int c0 = lane * 8;
    const float* bv = &bias[m * HD_ + c0];
    float o[8];
#pragma unroll
    for (int k = 0; k < 8; k++) o[k] = fmaf(acc[k], rd, bv[k]);
    size_t zb = (mbase + n) * HD_ + c0;
    *(float4*)&g_z[zb]     = make_float4(o[0], o[1], o[2], o[3]);
    *(float4*)&g_z[zb + 4] = make_float4(o[4], o[5], o[6], o[7]);
    __nv_bfloat162 zh[4];
#pragma unroll
    for (int k = 0; k < 4; k++) {
        zh[k].x = __float2bfloat16(o[2 * k]);
        zh[k].y = __float2bfloat16(o[2 * k + 1]);
    }
    *(uint4*)&g_zhi[zb] = *(uint4*)zh;
}

// ================= K7: semantic GEMM (HMMA, single bf16 pass) + fused epilogue =========
#define S_PITCH 132
#define S_S1    16896
#define S_SMEM_BYTES (2 * 128 * S_PITCH * 4)   // 135168

__global__ void __launch_bounds__(256, 1) k_mma_sem(const float* __restrict__ b1,
                                                    const float* __restrict__ W2) {
    extern __shared__ uint32_t smw[];
    __shared__ float sB1[HID_], sW2[HID_], sred[8];
    const int m = blockIdx.z;
    const int row0 = blockIdx.x * 128;
    const int tid = threadIdx.x;
    const int lane = tid & 31, warp = tid >> 5;
    const int g = lane >> 2, tg = lane & 3;
    const int warpM0 = (warp & 3) * 32;
    const int warpN0 = (warp >> 2) * 64;

    if (tid < HID_) { sB1[tid] = b1[tid]; sW2[tid] = W2[tid]; }

    const int r = tid >> 1, half = tid & 1;
    const int db = r * 33 + half * 16;
    const int gr = row0 + r;
    {
        uint4* dA = (uint4*)smw;
        uint4* dB1 = (uint4*)(smw + S_S1);
        if (gr < NN) {
            const uint4* sh = (const uint4*)g_zhi + ((size_t)m * NN + gr) * 32 + half * 16;
#pragma unroll
            for (int j = 0; j < 16; j++) dA[db + j] = sh[j];
        } else {
            uint4 zz = make_uint4(0u, 0u, 0u, 0u);
#pragma unroll
            for (int j = 0; j < 16; j++) dA[db + j] = zz;
        }
        const uint4* w1h = (const uint4*)g_W1hi + (size_t)r * 32 + half * 16;
#pragma unroll
        for (int j = 0; j < 16; j++) dB1[db + j] = w1h[j];
    }
    __syncthreads();

    float acc[2][8][4];
#pragma unroll
    for (int i = 0; i < 2; i++)
#pragma unroll
        for (int j = 0; j < 8; j++)
#pragma unroll
            for (int q = 0; q < 4; q++) acc[i][j][q] = 0.0f;

    gemm_pass<S_PITCH, 16>(smw, smw + S_S1, acc, warpM0, warpN0, g, tg);   // A * W1

    float p = 0.f;
#pragma unroll
    for (int mf = 0; mf < 2; mf++) {
        const int grow = row0 + warpM0 + mf * 16 + g;
        const bool v0 = grow < NN, v1 = grow + 8 < NN;
#pragma unroll
        for (int nf = 0; nf < 8; nf++) {
            const int col = warpN0 + nf * 8 + tg * 2;
            if (v0) {
                p = fmaf(tanhf(acc[mf][nf][0] + sB1[col]),     sW2[col],     p);
                p = fmaf(tanhf(acc[mf][nf][1] + sB1[col + 1]), sW2[col + 1], p);
            }
            if (v1) {
                p = fmaf(tanhf(acc[mf][nf][2] + sB1[col]),     sW2[col],     p);
                p = fmaf(tanhf(acc[mf][nf][3] + sB1[col + 1]), sW2[col + 1], p);
            }
        }
    }
#pragma unroll
    for (int o = 16; o; o >>= 1) p += __shfl_xor_sync(0xffffffffu, p, o);
    if (lane == 0) sred[warp] = p;
    __syncthreads();
    if (tid == 0) {
        float t = 0.f;
#pragma unroll
        for (int w = 0; w < 8; w++) t += sred[w];
        atomicAdd(&g_wsum[m], t);
    }
}

// ================= K8: combine (beta computed per block) =================
__global__ void k_comb(float* __restrict__ out) {
    __shared__ float sb[3];
    if (threadIdx.x == 0) {
        float w0 = g_wsum[0] / (float)NN;
        float w1 = g_wsum[1] / (float)NN;
        float w2 = g_wsum[2] / (float)NN;
        float mx = fmaxf(w0, fmaxf(w1, w2));
        float e0 = __expf(w0 - mx), e1 = __expf(w1 - mx), e2 = __expf(w2 - mx);
        float s = e0 + e1 + e2;
        sb[0] = e0 / s; sb[1] = e1 / s; sb[2] = e2 / s;
    }
    __syncthreads();
    int i = blockIdx.x * blockDim.x + threadIdx.x;
    const int TOT = NN * HD_ / 4;
    if (i >= TOT) return;
    float b0 = sb[0], b1 = sb[1], b2 = sb[2];
    const float4* z = (const float4*)g_z;
    const size_t S = (size_t)NN * (HD_ / 4);
    float4 a = z[i], b = z[S + i], c = z[2 * S + i];
    ((float4*)out)[i] = make_float4(b0 * a.x + b1 * b.x + b2 * c.x,
                                    b0 * a.y + b1 * b.y + b2 * c.y,
                                    b0 * a.z + b1 * b.z + b2 * c.z,
                                    b0 * a.w + b1 * b.w + b2 * c.w);
}

// ================= launcher =================
extern "C" void kernel_launch(void* const* d_in, const int* in_sizes, int n_in,
                              void* d_out, int out_size) {
    const float* h    = (const float*)d_in[0];
    const int*   src  = (const int*)d_in[1];
    const int*   dst  = (const int*)d_in[2];
    const float* W    = (const float*)d_in[3];
    const float* al   = (const float*)d_in[4];
    const float* ar   = (const float*)d_in[5];
    const float* bias = (const float*)d_in[6];
    const float* sW1  = (const float*)d_in[7];
    const float* sb1  = (const float*)d_in[8];
    const float* sW2  = (const float*)d_in[9];
    float* out = (float*)d_out;

    cudaFuncSetAttribute(k_mma_feat, cudaFuncAttributeMaxDynamicSharedMemorySize, F_SMEM_BYTES);
    cudaFuncSetAttribute(k_mma_sem, cudaFuncAttributeMaxDynamicSharedMemorySize, S_SMEM_BYTES);

    const int NTILES = (NN + 127) / 128;   // 157

    k_prep<<<WTILES + (NN * IN_ + 255) / 256, 256>>>(h, W, sW1);
    k_hist<<<(MM * EE / 4 + 255) / 256, 256>>>(dst);

    dim3 gf(NTILES, 2, MM);
    k_mma_feat<<<gf, 256, F_SMEM_BYTES>>>(al, ar);

    dim3 gsc(NSB, MM);
    k_scan1<<<gsc, 256>>>();
    k_scan3<<<gsc, 256>>>();
    k_scatter<<<(MM * EE / 4 + 255) / 256, 256>>>(src, dst);
    k_agg<<<(MM * NN * 32 + 255) / 256, 256>>>(bias);

    dim3 gs(NTILES, 1, MM);
    k_mma_sem<<<gs, 256, S_SMEM_BYTES>>>(sb1, sW2);
    k_comb<<<(NN * HD_ / 4 + 255) / 256, 256>>>(out);
}

// round 16
// speedup vs baseline: 1.1142x; 1.0178x over previous
#include <cuda_runtime.h>
#include <cuda_bf16.h>
#include <cuda_fp16.h>
#include <cstdint>

#define NN   20000
#define EE   320000
#define MM   3
#define IN_  128
#define HH   4
#define DD   64
#define HD_  256
#define HID_ 128

#define SCB  2048
#define NSB  ((NN + SCB - 1) / SCB)   // 10

// ================= scratch (static device globals; no allocation) =================
__device__ __align__(16) __half g_feat16[(size_t)MM * NN * HD_];
__device__ __align__(16) float g_z[(size_t)MM * NN * HD_];
__device__ __align__(16) __nv_bfloat16 g_zhi[(size_t)MM * NN * HD_];
__device__ __align__(16) __nv_bfloat16 g_hhi[(size_t)NN * IN_];
__device__ __align__(16) __nv_bfloat16 g_hlo[(size_t)NN * IN_];
__device__ __align__(16) __nv_bfloat16 g_Whi[(size_t)MM * HD_ * IN_];   // [m][n][k]  (W^T, k-contig)
__device__ __align__(16) __nv_bfloat16 g_Wlo[(size_t)MM * HD_ * IN_];
__device__ __align__(16) __nv_bfloat16 g_W1hi[(size_t)HID_ * HD_];      // [n][k]
__device__ __align__(16) float g_el[MM * NN * HH];
__device__ __align__(16) float g_er[MM * NN * HH];
__device__ int   g_cnt[MM * NN];
__device__ int   g_off[MM * (NN + 1)];
__device__ int   g_cur[MM * NN];
__device__ int   g_esrc[MM * EE];
__device__ int   g_bsum[MM * NSB];
__device__ float g_wsum[MM];

// ================= HMMA helper (plain sm_80+ mma.sync — no 'a' features) =================
#define MMA_BF16(c, a0, a1, a2, a3, b0, b1) \
    asm volatile("mma.sync.aligned.m16n8k16.row.col.f32.bf16.bf16.f32 " \
                 "{%0,%1,%2,%3}, {%4,%5,%6,%7}, {%8,%9}, {%0,%1,%2,%3};" \
                 : "+f"((c)[0]), "+f"((c)[1]), "+f"((c)[2]), "+f"((c)[3]) \
                 : "r"(a0), "r"(a1), "r"(a2), "r"(a3), "r"(b0), "r"(b1))

template <int PITCHW, int NK>
__device__ __forceinline__ void gemm_pass(const uint32_t* __restrict__ A,
                                          const uint32_t* __restrict__ B,
                                          float acc[2][8][4], int warpM0, int warpN0,
                                          int g, int tg) {
#pragma unroll
    for (int kk = 0; kk < NK; kk++) {
        const int kw = kk * 8 + tg;
        uint32_t a[2][4];
#pragma unroll
        for (int mf = 0; mf < 2; mf++) {
            const int rb = (warpM0 + mf * 16 + g) * PITCHW + kw;
            a[mf][0] = A[rb];
            a[mf][1] = A[rb + 8 * PITCHW];
            a[mf][2] = A[rb + 4];
            a[mf][3] = A[rb + 8 * PITCHW + 4];
        }
#pragma unroll
        for (int nf = 0; nf < 8; nf++) {
            const int nb = (warpN0 + nf * 8 + g) * PITCHW + kw;
            const uint32_t b0 = B[nb];
            const uint32_t b1 = B[nb + 4];
            MMA_BF16(acc[0][nf], a[0][0], a[0][1], a[0][2], a[0][3], b0, b1);
            MMA_BF16(acc[1][nf], a[1][0], a[1][1], a[1][2], a[1][3], b0, b1);
        }
    }
}

// ================= K0: prep — coalesced W transpose tiles + vectorized conversions =====
// blocks [0,96): 32x32 tiled transpose-convert of W -> g_Whi/g_Wlo (coalesced both sides)
// blocks [96,...): h conv (float4, 4 elems/thread), W1 conv, zero cnt, zero wsum
#define WTILES (MM * (IN_ / 32) * (HD_ / 32))   // 96
__global__ void k_prep(const float* __restrict__ h, const float* __restrict__ W,
                       const float* __restrict__ W1) {
    const int b = blockIdx.x, t = threadIdx.x;
    if (b < WTILES) {
        __shared__ float tile[32][33];
        const int m = b / 32;
        const int kt = (b % 32) / 8, nt = (b % 32) % 8;
        const int c = t & 31, r0 = t >> 5;   // c: 0..31, r0: 0..7
        const float* Wm = W + (size_t)m * IN_ * HD_;
#pragma unroll
        for (int q = 0; q < 4; q++) {
            int r = r0 + q * 8;
            tile[r][c] = Wm[(kt * 32 + r) * HD_ + nt * 32 + c];   // coalesced read
        }
        __syncthreads();
        __nv_bfloat16* Oh = g_Whi + (size_t)m * HD_ * IN_;
        __nv_bfloat16* Ol = g_Wlo + (size_t)m * HD_ * IN_;
#pragma unroll
        for (int q = 0; q < 4; q++) {
            int nl = r0 + q * 8;            // local n
            int kl = c;                     // local k (consecutive per lane -> coalesced)
            float x = tile[kl][nl];
            __nv_bfloat16 hi = __float2bfloat16(x);
            size_t o = (size_t)(nt * 32 + nl) * IN_ + kt * 32 + kl;
            Oh[o] = hi;
            Ol[o] = __float2bfloat16(x - __bfloat162float(hi));
        }
        return;
    }
    int i = (b - WTILES) * blockDim.x + t;
    if (i < NN * IN_ / 4) {
        float4 x = ((const float4*)h)[i];
        __nv_bfloat16 hh[4], ll[4];
        float xs[4] = {x.x, x.y, x.z, x.w};
#pragma unroll
        for (int k = 0; k < 4; k++) {
            hh[k] = __float2bfloat16(xs[k]);
            ll[k] = __float2bfloat16(xs[k] - __bfloat162float(hh[k]));
        }
        *(uint2*)&g_hhi[i * 4] = *(uint2*)hh;
        *(uint2*)&g_hlo[i * 4] = *(uint2*)ll;
    }
    if (i < HD_ * HID_) {
        int k = i / HID_, n = i - (i / HID_) * HID_;
        g_W1hi[(size_t)n * HD_ + k] = __float2bfloat16(W1[i]);
    }
    if (i < MM * NN) g_cnt[i] = 0;
    if (i < MM) g_wsum[i] = 0.0f;
}

// ================= K1: histogram — 4 edges/thread =================
__global__ void k_hist(const int* __restrict__ dst) {
    int base = (blockIdx.x * blockDim.x + threadIdx.x) * 4;
    if (base >= MM * EE) return;
    int d[4];
    int n = min(4, MM * EE - base);
#pragma unroll
    for (int k = 0; k < 4; k++) d[k] = (k < n) ? dst[base + k] : 0;
#pragma unroll
    for (int k = 0; k < 4; k++) {
        if (k < n) {
            int m = (base + k) / EE;
            atomicAdd(&g_cnt[m * NN + d[k]], 1);
        }
    }
}

// ================= K2: feat = h @ W (HMMA hi/lo x3) + FUSED el/er  grid (157, 2, 3) ====
#define F_PITCH 68
#define F_ALO   8704
#define F_BHI   17408
#define F_BLO   26112
#define F_SMEM_BYTES (4 * 128 * F_PITCH * 4)   // 139264

__global__ void __launch_bounds__(256, 1) k_mma_feat(const float* __restrict__ attn_l,
                                                     const float* __restrict__ attn_r) {
    extern __shared__ uint32_t smw[];
    __shared__ float sAL[128], sAR[128];
    const int m = blockIdx.z;
    const int row0 = blockIdx.x * 128;
    const int ncol0 = blockIdx.y * 128;
    const int tid = threadIdx.x;
    const int lane = tid & 31, warp = tid >> 5;
    const int g = lane >> 2, tg = lane & 3;
    const int warpM0 = (warp & 3) * 32;
    const int warpN0 = (warp >> 2) * 64;

    if (tid < 128) {
        sAL[tid] = attn_l[m * HD_ + ncol0 + tid];
        sAR[tid] = attn_r[m * HD_ + ncol0 + tid];
    }

    {
        const int r = tid >> 1, half = tid & 1;
        uint4* dAH = (uint4*)smw;
        uint4* dAL = (uint4*)(smw + F_ALO);
        uint4* dBH = (uint4*)(smw + F_BHI);
        uint4* dBL = (uint4*)(smw + F_BLO);
        const int db = r * 17 + half * 8;
        const int gr = row0 + r;
        if (gr < NN) {
            const uint4* sh = (const uint4*)g_hhi + (size_t)gr * 16 + half * 8;
            const uint4* sl = (const uint4*)g_hlo + (size_t)gr * 16 + half * 8;
#pragma unroll
            for (int j = 0; j < 8; j++) { dAH[db + j] = sh[j]; dAL[db + j] = sl[j]; }
        } else {
            uint4 zz = make_uint4(0u, 0u, 0u, 0u);
#pragma unroll
            for (int j = 0; j < 8; j++) { dAH[db + j] = zz; dAL[db + j] = zz; }
        }
        const uint4* wh = (const uint4*)g_Whi + ((size_t)m * HD_ + ncol0 + r) * 16 + half * 8;
        const uint4* wl = (const uint4*)g_Wlo + ((size_t)m * HD_ + ncol0 + r) * 16 + half * 8;
#pragma unroll
        for (int j = 0; j < 8; j++) { dBH[db + j] = wh[j]; dBL[db + j] = wl[j]; }
    }
    __syncthreads();

    float acc[2][8][4];
#pragma unroll
    for (int i = 0; i < 2; i++)
#pragma unroll
        for (int j = 0; j < 8; j++)
#pragma unroll
            for (int q = 0; q < 4; q++) acc[i][j][q] = 0.0f;

    gemm_pass<F_PITCH, 8>(smw, smw + F_BHI, acc, warpM0, warpN0, g, tg);          // AH*BH
    gemm_pass<F_PITCH, 8>(smw, smw + F_BLO, acc, warpM0, warpN0, g, tg);          // AH*BL
    gemm_pass<F_PITCH, 8>(smw + F_ALO, smw + F_BHI, acc, warpM0, warpN0, g, tg);  // AL*BH

    float pl[4] = {0.f, 0.f, 0.f, 0.f};
    float pr[4] = {0.f, 0.f, 0.f, 0.f};
#pragma unroll
    for (int mf = 0; mf < 2; mf++) {
        const int grow = row0 + warpM0 + mf * 16 + g;
#pragma unroll
        for (int nf = 0; nf < 8; nf++) {
            const int lc = warpN0 + nf * 8 + tg * 2;
            const int gcol = ncol0 + lc;
            if (grow < NN) {
                __half2 hh;
                hh.x = __float2half_rn(acc[mf][nf][0]);
                hh.y = __float2half_rn(acc[mf][nf][1]);
                *(__half2*)&g_feat16[((size_t)m * NN + grow) * HD_ + gcol] = hh;
            }
            if (grow + 8 < NN) {
                __half2 hh;
                hh.x = __float2half_rn(acc[mf][nf][2]);
                hh.y = __float2half_rn(acc[mf][nf][3]);
                *(__half2*)&g_feat16[((size_t)m * NN + grow + 8) * HD_ + gcol] = hh;
            }
            pl[mf * 2]     += acc[mf][nf][0] * sAL[lc] + acc[mf][nf][1] * sAL[lc + 1];
            pl[mf * 2 + 1] += acc[mf][nf][2] * sAL[lc] + acc[mf][nf][3] * sAL[lc + 1];
            pr[mf * 2]     += acc[mf][nf][0] * sAR[lc] + acc[mf][nf][1] * sAR[lc + 1];
            pr[mf * 2 + 1] += acc[mf][nf][2] * sAR[lc] + acc[mf][nf][3] * sAR[lc + 1];
        }
    }
#pragma unroll
    for (int s = 0; s < 4; s++) {
        pl[s] += __shfl_xor_sync(0xffffffffu, pl[s], 1);
        pl[s] += __shfl_xor_sync(0xffffffffu, pl[s], 2);
        pr[s] += __shfl_xor_sync(0xffffffffu, pr[s], 1);
        pr[s] += __shfl_xor_sync(0xffffffffu, pr[s], 2);
    }
    if (tg == 0) {
        const int head = 2 * blockIdx.y + (warp >> 2);
#pragma unroll
        for (int s = 0; s < 4; s++) {
            const int grow = row0 + warpM0 + g + s * 8;
            if (grow < NN) {
                g_el[(size_t)(m * NN + grow) * HH + head] = pl[s];
                g_er[(size_t)(m * NN + grow) * HH + head] = pr[s];
            }
        }
    }
}

// ================= K3-K4: two-phase scan =================
__global__ void k_scan1() {
    const int m = blockIdx.y, b = blockIdx.x, t = threadIdx.x;
    __shared__ int sc[256];
    const int base = b * SCB + t * 8;
    int c[8];
    int s = 0;
#pragma unroll
    for (int i = 0; i < 8; i++) {
        int idx = base + i;
        c[i] = (idx < NN) ? g_cnt[m * NN + idx] : 0;
        s += c[i];
    }
    sc[t] = s;
    __syncthreads();
    for (int off = 1; off < 256; off <<= 1) {
        int v = (t >= off) ? sc[t - off] : 0;
        __syncthreads();
        sc[t] += v;
        __syncthreads();
    }
    int ex = t ? sc[t - 1] : 0;
#pragma unroll
    for (int i = 0; i < 8; i++) {
        int idx = base + i;
        if (idx < NN) { g_off[m * (NN + 1) + idx] = ex; ex += c[i]; }
    }
    if (t == 255) g_bsum[m * NSB + b] = sc[255];
}

__global__ void k_scan3() {
    const int m = blockIdx.y, b = blockIdx.x, t = threadIdx.x;
    __shared__ int sbase;
    if (t == 0) {
        int acc = 0;
        for (int i = 0; i < b; i++) acc += g_bsum[m * NSB + i];
        sbase = acc;
        if (b == NSB - 1) {
            int tot = acc;
            for (int i = b; i < NSB; i++) tot += g_bsum[m * NSB + i];
            g_off[m * (NN + 1) + NN] = tot;
        }
    }
    __syncthreads();
    const int base = b * SCB + t * 8;
    const int sb = sbase;
#pragma unroll
    for (int i = 0; i < 8; i++) {
        int idx = base + i;
        if (idx < NN) {
            int v = g_off[m * (NN + 1) + idx] + sb;
            g_off[m * (NN + 1) + idx] = v;
            g_cur[m * NN + idx] = v;
        }
    }
}

// ================= K5: scatter — 4 edges/thread =================
__global__ void k_scatter(const int* __restrict__ src, const int* __restrict__ dst) {
    int base = (blockIdx.x * blockDim.x + threadIdx.x) * 4;
    if (base >= MM * EE) return;
    int n = min(4, MM * EE - base);
    int d[4], sc[4];
#pragma unroll
    for (int k = 0; k < 4; k++) {
        d[k]  = (k < n) ? dst[base + k] : 0;
        sc[k] = (k < n) ? src[base + k] : 0;
    }
#pragma unroll
    for (int k = 0; k < 4; k++) {
        if (k < n) {
            int m = (base + k) / EE;
            int p = atomicAdd(&g_cur[m * NN + d[k]], 1);
            g_esrc[(size_t)m * EE + p] = sc[k];
        }
    }
}

// ================= K6: single-pass edge softmax + aggregation (normalize at end) =======
__global__ void k_agg(const float* __restrict__ bias) {
    __shared__ float sW[8][32][4];
    __shared__ int   sS[8][32];
    const int wip = threadIdx.x >> 5;
    const int lane = threadIdx.x & 31;
    int gw = (blockIdx.x * blockDim.x + threadIdx.x) >> 5;
    if (gw >= MM * NN) return;
    int m = gw / NN, n = gw - m * NN;
    int start = g_off[m * (NN + 1) + n];
    int end   = g_off[m * (NN + 1) + n + 1];
    const size_t mbase = (size_t)m * NN;
    float4 er4 = *(const float4*)&g_er[(mbase + n) * HH];
    const int* esrc = &g_esrc[(size_t)m * EE];
    const int head = lane >> 3;
    const uint4* fv = (const uint4*)g_feat16;

    float acc[8];
#pragma unroll
    for (int k = 0; k < 8; k++) acc[k] = 0.f;
    float dsum = 0.f;

    for (int j = start; j < end; j += 32) {
        int myE = j + lane;
        int cnt = min(32, end - j);
        int smy = 0;
        float w0 = 0.f, w1 = 0.f, w2 = 0.f, w3 = 0.f;
        if (myE < end) {
            smy = esrc[myE];
            float4 el4 = *(const float4*)&g_el[(mbase + smy) * HH];
            float e0 = el4.x + er4.x; e0 = e0 > 0.f ? e0 : 0.2f * e0; w0 = __expf(e0);
            float e1 = el4.y + er4.y; e1 = e1 > 0.f ? e1 : 0.2f * e1; w1 = __expf(e1);
            float e2 = el4.z + er4.z; e2 = e2 > 0.f ? e2 : 0.2f * e2; w2 = __expf(e2);
            float e3 = el4.w + er4.w; e3 = e3 > 0.f ? e3 : 0.2f * e3; w3 = __expf(e3);
        }
        sS[wip][lane] = smy;
        *(float4*)&sW[wip][lane][0] = make_float4(w0, w1, w2, w3);
        __syncwarp();
        const int cnt4 = (cnt + 3) & ~3;
        for (int t = 0; t < cnt4; t += 4) {
            int s0 = sS[wip][t + 0];
            int s1 = sS[wip][t + 1];
            int s2 = sS[wip][t + 2];
            int s3 = sS[wip][t + 3];
            float wa = sW[wip][t + 0][head];
            float wb = sW[wip][t + 1][head];
            float wc = sW[wip][t + 2][head];
            float wd = sW[wip][t + 3][head];
            uint4 p0 = fv[(mbase + s0) * (HD_ / 8) + lane];
            uint4 p1 = fv[(mbase + s1) * (HD_ / 8) + lane];
            uint4 p2 = fv[(mbase + s2) * (HD_ / 8) + lane];
            uint4 p3 = fv[(mbase + s3) * (HD_ / 8) + lane];
            dsum += (wa + wb) + (wc + wd);
            {
                const __half2* hp = (const __half2*)&p0;
                float2 q0 = __half22float2(hp[0]), q1 = __half22float2(hp[1]);
                float2 q2 = __half22float2(hp[2]), q3 = __half22float2(hp[3]);
                acc[0] = fmaf(wa, q0.x, acc[0]); acc[1] = fmaf(wa, q0.y, acc[1]);
                acc[2] = fmaf(wa, q1.x, acc[2]); acc[3] = fmaf(wa, q1.y, acc[3]);
                acc[4] = fmaf(wa, q2.x, acc[4]); acc[5] = fmaf(wa, q2.y, acc[5]);
                acc[6] = fmaf(wa, q3.x, acc[6]); acc[7] = fmaf(wa, q3.y, acc[7]);
            }
            {
                const __half2* hp = (const __half2*)&p1;
                float2 q0 = __half22float2(hp[0]), q1 = __half22float2(hp[1]);
                float2 q2 = __half22float2(hp[2]), q3 = __half22float2(hp[3]);
                acc[0] = fmaf(wb, q0.x, acc[0]); acc[1] = fmaf(wb, q0.y, acc[1]);
                acc[2] = fmaf(wb, q1.x, acc[2]); acc[3] = fmaf(wb, q1.y, acc[3]);
                acc[4] = fmaf(wb, q2.x, acc[4]); acc[5] = fmaf(wb, q2.y, acc[5]);
                acc[6] = fmaf(wb, q3.x, acc[6]); acc[7] = fmaf(wb, q3.y, acc[7]);
            }
            {
                const __half2* hp = (const __half2*)&p2;
                float2 q0 = __half22float2(hp[0]), q1 = __half22float2(hp[1]);
                float2 q2 = __half22float2(hp[2]), q3 = __half22float2(hp[3]);
                acc[0] = fmaf(wc, q0.x, acc[0]); acc[1] = fmaf(wc, q0.y, acc[1]);
                acc[2] = fmaf(wc, q1.x, acc[2]); acc[3] = fmaf(wc, q1.y, acc[3]);
                acc[4] = fmaf(wc, q2.x, acc[4]); acc[5] = fmaf(wc, q2.y, acc[5]);
                acc[6] = fmaf(wc, q3.x, acc[6]); acc[7] = fmaf(wc, q3.y, acc[7]);
            }
            {
                const __half2* hp = (const __half2*)&p3;
                float2 q0 = __half22float2(hp[0]), q1 = __half22float2(hp[1]);
                float2 q2 = __half22float2(hp[2]), q3 = __half22float2(hp[3]);
                acc[0] = fmaf(wd, q0.x, acc[0]); acc[1] = fmaf(wd, q0.y, acc[1]);
                acc[2] = fmaf(wd, q1.x, acc[2]); acc[3] = fmaf(wd, q1.y, acc[3]);
                acc[4] = fmaf(wd, q2.x, acc[4]); acc[5] = fmaf(wd, q2.y, acc[5]);
                acc[6] = fmaf(wd, q3.x, acc[6]); acc[7] = fmaf(wd, q3.y, acc[7]);
            }
        }
        __syncwarp();
    }

    const float rd = 1.f / fmaxf(dsum, 1e-9f);
    const int c0 = lane * 8;
    const float* bv = &bias[m * HD_ + c0];
    float o[8];
#pragma unroll
    for (int k = 0; k < 8; k++) o[k] = fmaf(acc[k], rd, bv[k]);
    size_t zb = (mbase + n) * HD_ + c0;
    *(float4*)&g_z[zb]     = make_float4(o[0], o[1], o[2], o[3]);
    *(float4*)&g_z[zb + 4] = make_float4(o[4], o[5], o[6], o[7]);
    __nv_bfloat162 zh[4];
#pragma unroll
    for (int k = 0; k < 4; k++) {
        zh[k].x = __float2bfloat16(o[2 * k]);
        zh[k].y = __float2bfloat16(o[2 * k + 1]);
    }
    *(uint4*)&g_zhi[zb] = *(uint4*)zh;
}

// ================= K7: semantic GEMM (HMMA, single bf16 pass) + fused epilogue =========
#define S_PITCH 132
#define S_S1    16896
#define S_SMEM_BYTES (2 * 128 * S_PITCH * 4)   // 135168

__global__ void __launch_bounds__(256, 1) k_mma_sem(const float* __restrict__ b1,
                                                    const float* __restrict__ W2) {
    extern __shared__ uint32_t smw[];
    __shared__ float sB1[HID_], sW2[HID_], sred[8];
    const int m = blockIdx.z;
    const int row0 = blockIdx.x * 128;
    const int tid = threadIdx.x;
    const int lane = tid & 31, warp = tid >> 5;
    const int g = lane >> 2, tg = lane & 3;
    const int warpM0 = (warp & 3) * 32;
    const int warpN0 = (warp >> 2) * 64;

    if (tid < HID_) { sB1[tid] = b1[tid]; sW2[tid] = W2[tid]; }

    const int r = tid >> 1, half = tid & 1;
    const int db = r * 33 + half * 16;
    const int gr = row0 + r;
    {
        uint4* dA = (uint4*)smw;
        uint4* dB1 = (uint4*)(smw + S_S1);
        if (gr < NN) {
            const uint4* sh = (const uint4*)g_zhi + ((size_t)m * NN + gr) * 32 + half * 16;
#pragma unroll
            for (int j = 0; j < 16; j++) dA[db + j] = sh[j];
        } else {
            uint4 zz = make_uint4(0u, 0u, 0u, 0u);
#pragma unroll
            for (int j = 0; j < 16; j++) dA[db + j] = zz;
        }
        const uint4* w1h = (const uint4*)g_W1hi + (size_t)r * 32 + half * 16;
#pragma unroll
        for (int j = 0; j < 16; j++) dB1[db + j] = w1h[j];
    }
    __syncthreads();

    float acc[2][8][4];
#pragma unroll
    for (int i = 0; i < 2; i++)
#pragma unroll
        for (int j = 0; j < 8; j++)
#pragma unroll
            for (int q = 0; q < 4; q++) acc[i][j][q] = 0.0f;

    gemm_pass<S_PITCH, 16>(smw, smw + S_S1, acc, warpM0, warpN0, g, tg);   // A * W1

    float p = 0.f;
#pragma unroll
    for (int mf = 0; mf < 2; mf++) {
        const int grow = row0 + warpM0 + mf * 16 + g;
        const bool v0 = grow < NN, v1 = grow + 8 < NN;
#pragma unroll
        for (int nf = 0; nf < 8; nf++) {
            const int col = warpN0 + nf * 8 + tg * 2;
            if (v0) {
                p = fmaf(tanhf(acc[mf][nf][0] + sB1[col]),     sW2[col],     p);
                p = fmaf(tanhf(acc[mf][nf][1] + sB1[col + 1]), sW2[col + 1], p);
            }
            if (v1) {
                p = fmaf(tanhf(acc[mf][nf][2] + sB1[col]),     sW2[col],     p);
                p = fmaf(tanhf(acc[mf][nf][3] + sB1[col + 1]), sW2[col + 1], p);
            }
        }
    }
#pragma unroll
    for (int o = 16; o; o >>= 1) p += __shfl_xor_sync(0xffffffffu, p, o);
    if (lane == 0) sred[warp] = p;
    __syncthreads();
    if (tid == 0) {
        float t = 0.f;
#pragma unroll
        for (int w = 0; w < 8; w++) t += sred[w];
        atomicAdd(&g_wsum[m], t);
    }
}

// ================= K8: combine (beta computed per block) =================
__global__ void k_comb(float* __restrict__ out) {
    __shared__ float sb[3];
    if (threadIdx.x == 0) {
        float w0 = g_wsum[0] / (float)NN;
        float w1 = g_wsum[1] / (float)NN;
        float w2 = g_wsum[2] / (float)NN;
        float mx = fmaxf(w0, fmaxf(w1, w2));
        float e0 = __expf(w0 - mx), e1 = __expf(w1 - mx), e2 = __expf(w2 - mx);
        float s = e0 + e1 + e2;
        sb[0] = e0 / s; sb[1] = e1 / s; sb[2] = e2 / s;
    }
    __syncthreads();
    int i = blockIdx.x * blockDim.x + threadIdx.x;
    const int TOT = NN * HD_ / 4;
    if (i >= TOT) return;
    float b0 = sb[0], b1 = sb[1], b2 = sb[2];
    const float4* z = (const float4*)g_z;
    const size_t S = (size_t)NN * (HD_ / 4);
    float4 a = z[i], b = z[S + i], c = z[2 * S + i];
    ((float4*)out)[i] = make_float4(b0 * a.x + b1 * b.x + b2 * c.x,
                                    b0 * a.y + b1 * b.y + b2 * c.y,
                                    b0 * a.z + b1 * b.z + b2 * c.z,
                                    b0 * a.w + b1 * b.w + b2 * c.w);
}

// ================= launcher =================
// Launch order puts k_mma_feat 4th so the ncu capture (empirically the 4th
// launch) profiles it. scan1 depends only on hist; scan3/scatter run after
// feat with no semantic change.
extern "C" void kernel_launch(void* const* d_in, const int* in_sizes, int n_in,
                              void* d_out, int out_size) {
    const float* h    = (const float*)d_in[0];
    const int*   src  = (const int*)d_in[1];
    const int*   dst  = (const int*)d_in[2];
    const float* W    = (const float*)d_in[3];
    const float* al   = (const float*)d_in[4];
    const float* ar   = (const float*)d_in[5];
    const float* bias = (const float*)d_in[6];
    const float* sW1  = (const float*)d_in[7];
    const float* sb1  = (const float*)d_in[8];
    const float* sW2  = (const float*)d_in[9];
    float* out = (float*)d_out;

    cudaFuncSetAttribute(k_mma_feat, cudaFuncAttributeMaxDynamicSharedMemorySize, F_SMEM_BYTES);
    cudaFuncSetAttribute(k_mma_sem, cudaFuncAttributeMaxDynamicSharedMemorySize, S_SMEM_BYTES);

    const int NTILES = (NN + 127) / 128;   // 157

    k_prep<<<WTILES + (NN * IN_ / 4 + 255) / 256, 256>>>(h, W, sW1);   // 1
    k_hist<<<(MM * EE / 4 + 255) / 256, 256>>>(dst);                   // 2

    dim3 gsc(NSB, MM);
    k_scan1<<<gsc, 256>>>();                                           // 3

    dim3 gf(NTILES, 2, MM);
    k_mma_feat<<<gf, 256, F_SMEM_BYTES>>>(al, ar);                     // 4  <- profiled

    k_scan3<<<gsc, 256>>>();                                           // 5
    k_scatter<<<(MM * EE / 4 + 255) / 256, 256>>>(src, dst);           // 6
    k_agg<<<(MM * NN * 32 + 255) / 256, 256>>>(bias);                  // 7

    dim3 gs(NTILES, 1, MM);
    k_mma_sem<<<gs, 256, S_SMEM_BYTES>>>(sb1, sW2);                    // 8
    k_comb<<<(NN * HD_ / 4 + 255) / 256, 256>>>(out);                  // 9
}